// round 7
// baseline (speedup 1.0000x reference)
#include <cuda_runtime.h>

#define F_NUM 20000
#define H_NUM 40000
#define NALL  60000
#define E_NUM 640000
#define D_DIM 128
#define A_DIM 64
#define B_NUM 256
#define KSPLIT 50
#define KCH (F_NUM / KSPLIT)   // 400

// p_k tiling: 64 rows per block, processed as 8 batches of 8 rows.
#define PT_ROWS 64
#define PB1 ((F_NUM + PT_ROWS - 1) / PT_ROWS)   // 313
#define PB2 ((NALL + PT_ROWS - 1) / PT_ROWS)    // 938

// s_k layout: 8 warps/block, 4 edges/warp -> 32 edges per block.
#define S_EDGES_PER_BLOCK 32
#define S_GRID (E_NUM / S_EDGES_PER_BLOCK)   // 20000
static_assert(S_GRID * S_EDGES_PER_BLOCK == E_NUM, "s_k grid must cover all edges");
static_assert(KSPLIT * KCH == F_NUM, "split-K must tile F exactly");

// ---- scratch (static device globals; no allocation) ----
__device__ float g_P1[F_NUM * A_DIM];
__device__ float g_P2[NALL * A_DIM];
__device__ float g_scores[E_NUM];
__device__ float g_context[F_NUM * D_DIM];
__device__ int   g_cp[E_NUM];
__device__ int   g_fci[E_NUM];
__device__ int   g_is32[2];
__device__ int   g_segstart[F_NUM + 1];
__device__ float g_partial[KSPLIT * B_NUM * D_DIM];

__device__ __forceinline__ float tanh_hw(float x) {
    float y;
    asm("tanh.approx.f32 %0, %1;" : "=f"(y) : "f"(x));
    return y;
}

// ---------------------------------------------------------------------------
// int32/int64 index detection (probe tail as int64; int32 data yields
// high-word >= NALL).
// ---------------------------------------------------------------------------
__global__ void detect_k(const void* cp, const void* fci) {
    if (threadIdx.x != 0 || blockIdx.x != 0) return;
    const long long* p = (const long long*)cp;
    long long m = 0;
    for (int j = 1; j <= 8; ++j) {
        long long v = p[E_NUM / 2 - j];
        if (v < 0) v = (1LL << 40);
        if (v > m) m = v;
    }
    g_is32[0] = (m >= (long long)NALL) ? 1 : 0;
    const long long* q = (const long long*)fci;
    m = 0;
    for (int j = 1; j <= 8; ++j) {
        long long v = q[E_NUM / 2 - j];
        if (v < 0) v = (1LL << 40);
        if (v > m) m = v;
    }
    g_is32[1] = (m >= (long long)NALL) ? 1 : 0;
}

// ---------------------------------------------------------------------------
// convseg_k: fused index conversion + segment-boundary fill.
// segstart[f] = first e with cp[e] >= f (cp sorted). Each boundary written by
// exactly one thread -> deterministic.
// ---------------------------------------------------------------------------
__device__ __forceinline__ int idx_at(const void* p, int is32, int e) {
    return is32 ? ((const int*)p)[e] : (int)((const long long*)p)[e];
}

__global__ void convseg_k(const void* cp, const void* fci) {
    int e = blockIdx.x * blockDim.x + threadIdx.x;
    if (e >= E_NUM) return;
    const int is0 = g_is32[0], is1 = g_is32[1];
    const int c = idx_at(cp, is0, e);
    g_cp[e] = c;
    g_fci[e] = idx_at(fci, is1, e);
    const int prev = (e == 0) ? -1 : idx_at(cp, is0, e - 1);
    for (int f = prev + 1; f <= c; ++f) g_segstart[f] = e;
    if (e == E_NUM - 1)
        for (int f = c + 1; f <= F_NUM; ++f) g_segstart[f] = E_NUM;
}

// ---------------------------------------------------------------------------
// P kernel v3: double-buffered smem staging + shuffle reduction.
// Thread map: a = tid>>2 (output col), h = tid&3 (d-quarter of 32).
// The 4 quarters of one (row, a) live in adjacent lanes -> butterfly reduce.
// One __syncthreads per 8-row batch; next batch prefetched into registers.
// ---------------------------------------------------------------------------
__global__ __launch_bounds__(256) void p_k(const float* __restrict__ feat,
                                           const float* __restrict__ hid,
                                           const float* __restrict__ w) {
    const int tid = threadIdx.x;
    const int a = tid >> 2;
    const int h = tid & 3;

    const bool reg2 = (blockIdx.x >= PB1);
    const int row0 = (reg2 ? (blockIdx.x - PB1) : blockIdx.x) * PT_ROWS;
    const int limit = reg2 ? NALL : F_NUM;
    const int wbase = reg2 ? 128 : 0;

    float wr[32];
#pragma unroll
    for (int j = 0; j < 32; ++j)
        wr[j] = w[(wbase + h * 32 + j) * A_DIM + a];

    __shared__ float4 stage[2][8][32];   // 2 x (8 rows x 128 floats)

    // staging role: warp ww stages row (batch*8 + ww), lane c4 stages float4 c4
    const int ww = tid >> 5;
    const int c4 = tid & 31;

    // prefetch batch 0
    float4 pv = make_float4(0.f, 0.f, 0.f, 0.f);
    {
        const int row = row0 + ww;
        if (row < limit) {
            const float* src;
            if (!reg2) src = feat + (size_t)row * D_DIM;
            else       src = (row < F_NUM) ? (feat + (size_t)row * D_DIM)
                                           : (hid + (size_t)(row - F_NUM) * D_DIM);
            pv = ((const float4*)src)[c4];
        }
    }

    for (int b = 0; b < PT_ROWS / 8; ++b) {
        const int buf = b & 1;
        stage[buf][ww][c4] = pv;
        __syncthreads();

        // prefetch next batch while computing this one
        if (b + 1 < PT_ROWS / 8) {
            const int row = row0 + (b + 1) * 8 + ww;
            pv = make_float4(0.f, 0.f, 0.f, 0.f);
            if (row < limit) {
                const float* src;
                if (!reg2) src = feat + (size_t)row * D_DIM;
                else       src = (row < F_NUM) ? (feat + (size_t)row * D_DIM)
                                               : (hid + (size_t)(row - F_NUM) * D_DIM);
                pv = ((const float4*)src)[c4];
            }
        }

#pragma unroll
        for (int rr = 0; rr < 8; ++rr) {
            const float4* s4 = &stage[buf][rr][h * 8];
            float a0 = 0.f, a1 = 0.f, a2 = 0.f, a3 = 0.f;
#pragma unroll
            for (int j = 0; j < 8; ++j) {
                const float4 v = s4[j];
                a0 += v.x * wr[4 * j + 0];
                a1 += v.y * wr[4 * j + 1];
                a2 += v.z * wr[4 * j + 2];
                a3 += v.w * wr[4 * j + 3];
            }
            float part = (a0 + a1) + (a2 + a3);
            part += __shfl_xor_sync(0xffffffffu, part, 1);
            part += __shfl_xor_sync(0xffffffffu, part, 2);
            if (h == 0) {
                const int row = row0 + b * 8 + rr;
                if (row < limit) {
                    float* dst = reg2 ? (g_P2 + (size_t)row * A_DIM)
                                      : (g_P1 + (size_t)row * A_DIM);
                    dst[a] = part;
                }
            }
        }
        __syncthreads();   // WAR: stage[buf] reused at b+2; single barrier per batch pair
    }
}

// ---------------------------------------------------------------------------
// S kernel: 8-lane cooperative per edge -> coalesced row reads (2 lines/row).
// ---------------------------------------------------------------------------
__global__ __launch_bounds__(256) void s_k(const float* __restrict__ bias,
                                           const float* __restrict__ u,
                                           const float* __restrict__ corr) {
    const int tid = threadIdx.x;
    const int lane = tid & 31;
    const int grp = lane >> 3;
    const int l = lane & 7;
    const int warp = (blockIdx.x * 256 + tid) >> 5;
    const int e = warp * 4 + grp;

    const float4 b0 = ((const float4*)bias)[l];
    const float4 b1 = ((const float4*)bias)[l + 8];
    const float4 u0 = ((const float4*)u)[l];
    const float4 u1 = ((const float4*)u)[l + 8];

    const int c = g_cp[e];
    const int fi = g_fci[e];
    const float4* p1 = (const float4*)(g_P1 + (size_t)c * A_DIM);
    const float4* p2 = (const float4*)(g_P2 + (size_t)fi * A_DIM);
    const float4 x0 = p1[l], x1 = p1[l + 8];
    const float4 y0 = p2[l], y1 = p2[l + 8];

    float t = tanh_hw(x0.x + y0.x + b0.x) * u0.x
            + tanh_hw(x0.y + y0.y + b0.y) * u0.y
            + tanh_hw(x0.z + y0.z + b0.z) * u0.z
            + tanh_hw(x0.w + y0.w + b0.w) * u0.w
            + tanh_hw(x1.x + y1.x + b1.x) * u1.x
            + tanh_hw(x1.y + y1.y + b1.y) * u1.y
            + tanh_hw(x1.z + y1.z + b1.z) * u1.z
            + tanh_hw(x1.w + y1.w + b1.w) * u1.w;

    t += __shfl_xor_sync(0xffffffffu, t, 1);
    t += __shfl_xor_sync(0xffffffffu, t, 2);
    t += __shfl_xor_sync(0xffffffffu, t, 4);
    if (l == 0) g_scores[e] = __expf(t) * corr[e];
}

// ---------------------------------------------------------------------------
// C kernel: warp per feature segment, precomputed bounds, 4-deep pipeline.
// ---------------------------------------------------------------------------
__device__ __forceinline__ const float4* emb_row(const float* feat, const float* hid, int fi) {
    return (const float4*)((fi < F_NUM) ? (feat + (size_t)fi * D_DIM)
                                        : (hid + (size_t)(fi - F_NUM) * D_DIM));
}

__global__ __launch_bounds__(256) void c_k(const float* __restrict__ feat,
                                           const float* __restrict__ hid) {
    const int lane = threadIdx.x & 31;
    const int f = blockIdx.x * 8 + (threadIdx.x >> 5);
    if (f >= F_NUM) return;

    const int lo = g_segstart[f];
    const int hiN = g_segstart[f + 1];

    float4 acc = make_float4(0.f, 0.f, 0.f, 0.f);
    float den = 0.f;
    int e = lo;
    for (; e + 4 <= hiN; e += 4) {
        const float s0 = g_scores[e + 0];
        const float s1 = g_scores[e + 1];
        const float s2 = g_scores[e + 2];
        const float s3 = g_scores[e + 3];
        const float4 v0 = emb_row(feat, hid, g_fci[e + 0])[lane];
        const float4 v1 = emb_row(feat, hid, g_fci[e + 1])[lane];
        const float4 v2 = emb_row(feat, hid, g_fci[e + 2])[lane];
        const float4 v3 = emb_row(feat, hid, g_fci[e + 3])[lane];
        acc.x += s0 * v0.x + s1 * v1.x + s2 * v2.x + s3 * v3.x;
        acc.y += s0 * v0.y + s1 * v1.y + s2 * v2.y + s3 * v3.y;
        acc.z += s0 * v0.z + s1 * v1.z + s2 * v2.z + s3 * v3.z;
        acc.w += s0 * v0.w + s1 * v1.w + s2 * v2.w + s3 * v3.w;
        den += (s0 + s1) + (s2 + s3);
    }
    for (; e < hiN; ++e) {
        const float s = g_scores[e];
        const float4 v = emb_row(feat, hid, g_fci[e])[lane];
        acc.x += s * v.x; acc.y += s * v.y; acc.z += s * v.z; acc.w += s * v.w;
        den += s;
    }
    const float inv = (den != 0.f) ? (1.f / den) : 0.f;
    float4 o = make_float4(acc.x * inv, acc.y * inv, acc.z * inv, acc.w * inv);
    ((float4*)(g_context + (size_t)f * D_DIM))[lane] = o;
}

// ---------------------------------------------------------------------------
// G kernels: out[256,128] = values[256,F] @ context[F,128].
// Exact R5 configuration (measured good): 16 b-rows/block, acc[8], KSPLIT=50.
// ---------------------------------------------------------------------------
__global__ __launch_bounds__(256) void g1_k(const float* __restrict__ values) {
    const int tid = threadIdx.x;
    const int d = tid & 127;
    const int bh = tid >> 7;
    const int b0 = blockIdx.x * 16 + bh * 8;
    const int k0 = blockIdx.y * KCH;

    float acc[8];
#pragma unroll
    for (int i = 0; i < 8; ++i) acc[i] = 0.f;

    for (int k = k0; k < k0 + KCH; k += 4) {
        const float c0 = g_context[(size_t)(k + 0) * D_DIM + d];
        const float c1 = g_context[(size_t)(k + 1) * D_DIM + d];
        const float c2 = g_context[(size_t)(k + 2) * D_DIM + d];
        const float c3 = g_context[(size_t)(k + 3) * D_DIM + d];
#pragma unroll
        for (int i = 0; i < 8; ++i) {
            const float4 v = *(const float4*)(values + (size_t)(b0 + i) * F_NUM + k);
            acc[i] += v.x * c0 + v.y * c1 + v.z * c2 + v.w * c3;
        }
    }
    float* part = g_partial + (size_t)blockIdx.y * (B_NUM * D_DIM);
#pragma unroll
    for (int i = 0; i < 8; ++i) part[(size_t)(b0 + i) * D_DIM + d] = acc[i];
}

__global__ __launch_bounds__(256) void g2_k(float* __restrict__ out) {
    const int i = blockIdx.x * blockDim.x + threadIdx.x;
    if (i >= B_NUM * D_DIM) return;
    float s = 0.f;
#pragma unroll
    for (int j = 0; j < KSPLIT; ++j) s += g_partial[(size_t)j * (B_NUM * D_DIM) + i];
    out[i] = s;
}

// ---------------------------------------------------------------------------
extern "C" void kernel_launch(void* const* d_in, const int* in_sizes, int n_in,
                              void* d_out, int out_size) {
    const float* values = (const float*)d_in[0];
    const float* feat   = (const float*)d_in[1];
    const float* hid    = (const float*)d_in[2];
    const float* w      = (const float*)d_in[3];
    const float* bias   = (const float*)d_in[4];
    const float* u      = (const float*)d_in[5];
    const float* corr   = (const float*)d_in[6];
    const void*  cp     = d_in[7];
    const void*  fci    = d_in[8];
    float* out = (float*)d_out;

    detect_k<<<1, 32>>>(cp, fci);
    convseg_k<<<(E_NUM + 255) / 256, 256>>>(cp, fci);
    p_k<<<PB1 + PB2, 256>>>(feat, hid, w);
    s_k<<<S_GRID, 256>>>(bias, u, corr);
    c_k<<<F_NUM / 8, 256>>>(feat, hid);
    g1_k<<<dim3(16, KSPLIT), 256>>>(values);
    g2_k<<<(B_NUM * D_DIM + 255) / 256, 256>>>(out);
}

// round 8
// speedup vs baseline: 2.0528x; 2.0528x over previous
#include <cuda_runtime.h>

#define F_NUM 20000
#define H_NUM 40000
#define NALL  60000
#define E_NUM 640000
#define D_DIM 128
#define A_DIM 64
#define B_NUM 256
#define KSPLIT 50
#define KCH (F_NUM / KSPLIT)   // 400

// p_k tiling: 64 rows per block, processed in 8-row staged batches.
#define PT_ROWS 64
#define PB1 ((F_NUM + PT_ROWS - 1) / PT_ROWS)   // 313
#define PB2 ((NALL + PT_ROWS - 1) / PT_ROWS)    // 938

// s_k layout: 8 warps/block, 4 edges/warp -> 32 edges per block.
#define S_EDGES_PER_BLOCK 32
#define S_GRID (E_NUM / S_EDGES_PER_BLOCK)   // 20000
static_assert(S_GRID * S_EDGES_PER_BLOCK == E_NUM, "s_k grid must cover all edges");
static_assert(KSPLIT * KCH == F_NUM, "split-K must tile F exactly");

// ---- scratch (static device globals; no allocation) ----
__device__ float g_P1[F_NUM * A_DIM];
__device__ float g_P2[NALL * A_DIM];
__device__ float g_scores[E_NUM];
__device__ float g_context[F_NUM * D_DIM];
__device__ int   g_cp[E_NUM];
__device__ int   g_fci[E_NUM];
__device__ int   g_is32[2];
__device__ int   g_segstart[F_NUM + 1];
__device__ float g_partial[KSPLIT * B_NUM * D_DIM];

__device__ __forceinline__ float tanh_hw(float x) {
    float y;
    asm("tanh.approx.f32 %0, %1;" : "=f"(y) : "f"(x));
    return y;
}

// ---------------------------------------------------------------------------
// int32/int64 index detection (probe tail as int64; int32 data yields
// high-word >= NALL).
// ---------------------------------------------------------------------------
__global__ void detect_k(const void* cp, const void* fci) {
    if (threadIdx.x != 0 || blockIdx.x != 0) return;
    const long long* p = (const long long*)cp;
    long long m = 0;
    for (int j = 1; j <= 8; ++j) {
        long long v = p[E_NUM / 2 - j];
        if (v < 0) v = (1LL << 40);
        if (v > m) m = v;
    }
    g_is32[0] = (m >= (long long)NALL) ? 1 : 0;
    const long long* q = (const long long*)fci;
    m = 0;
    for (int j = 1; j <= 8; ++j) {
        long long v = q[E_NUM / 2 - j];
        if (v < 0) v = (1LL << 40);
        if (v > m) m = v;
    }
    g_is32[1] = (m >= (long long)NALL) ? 1 : 0;
}

// ---------------------------------------------------------------------------
// convseg_k: fused index conversion + segment-boundary fill.
// segstart[f] = first e with cp[e] >= f (cp sorted). Each boundary written by
// exactly one thread -> deterministic.
// ---------------------------------------------------------------------------
__device__ __forceinline__ int idx_at(const void* p, int is32, int e) {
    return is32 ? ((const int*)p)[e] : (int)((const long long*)p)[e];
}

__global__ void convseg_k(const void* cp, const void* fci) {
    int e = blockIdx.x * blockDim.x + threadIdx.x;
    if (e >= E_NUM) return;
    const int is0 = g_is32[0], is1 = g_is32[1];
    const int c = idx_at(cp, is0, e);
    g_cp[e] = c;
    g_fci[e] = idx_at(fci, is1, e);
    const int prev = (e == 0) ? -1 : idx_at(cp, is0, e - 1);
    for (int f = prev + 1; f <= c; ++f) g_segstart[f] = e;
    if (e == E_NUM - 1)
        for (int f = c + 1; f <= F_NUM; ++f) g_segstart[f] = E_NUM;
}

// ---------------------------------------------------------------------------
// P kernel v2 (EXACT R6 version, measured 75.8us): smem-staged rows,
// 4-way d-split, 256 threads. a = tid&63 (output col), h = tid>>6 (d-quarter).
// 8 rows staged coalescedly into smem; broadcast LDS reads; quarter partials
// reduced through smem by the h==0 group.
// ---------------------------------------------------------------------------
__global__ __launch_bounds__(256) void p_k(const float* __restrict__ feat,
                                           const float* __restrict__ hid,
                                           const float* __restrict__ w) {
    const int tid = threadIdx.x;
    const int a = tid & 63;
    const int h = tid >> 6;

    const bool reg2 = (blockIdx.x >= PB1);
    const int row0 = (reg2 ? (blockIdx.x - PB1) : blockIdx.x) * PT_ROWS;
    const int limit = reg2 ? NALL : F_NUM;
    const int wbase = reg2 ? 128 : 0;

    float wr[32];
#pragma unroll
    for (int j = 0; j < 32; ++j)
        wr[j] = w[(wbase + h * 32 + j) * A_DIM + a];

    __shared__ float4 stage[8][32];      // 8 rows x 128 floats
    __shared__ float red[3][8][64];      // partials from h = 1..3

    for (int b = 0; b < PT_ROWS / 8; ++b) {
        // stage 8 rows (one warp per row, fully coalesced)
        {
            const int rr = tid >> 5;
            const int c4 = tid & 31;
            const int row = row0 + b * 8 + rr;
            float4 v = make_float4(0.f, 0.f, 0.f, 0.f);
            if (row < limit) {
                const float* src;
                if (!reg2) src = feat + (size_t)row * D_DIM;
                else       src = (row < F_NUM) ? (feat + (size_t)row * D_DIM)
                                               : (hid + (size_t)(row - F_NUM) * D_DIM);
                v = ((const float4*)src)[c4];
            }
            stage[rr][c4] = v;
        }
        __syncthreads();

        float part[8];
#pragma unroll
        for (int rr = 0; rr < 8; ++rr) {
            const float4* s4 = &stage[rr][h * 8];
            float a0 = 0.f, a1 = 0.f, a2 = 0.f, a3 = 0.f;
#pragma unroll
            for (int j = 0; j < 8; ++j) {
                const float4 v = s4[j];
                a0 += v.x * wr[4 * j + 0];
                a1 += v.y * wr[4 * j + 1];
                a2 += v.z * wr[4 * j + 2];
                a3 += v.w * wr[4 * j + 3];
            }
            part[rr] = (a0 + a1) + (a2 + a3);
        }
        if (h) {
#pragma unroll
            for (int rr = 0; rr < 8; ++rr) red[h - 1][rr][a] = part[rr];
        }
        __syncthreads();
        if (!h) {
#pragma unroll
            for (int rr = 0; rr < 8; ++rr) {
                const int row = row0 + b * 8 + rr;
                if (row < limit) {
                    const float o = (part[rr] + red[0][rr][a])
                                  + (red[1][rr][a] + red[2][rr][a]);
                    float* dst = reg2 ? (g_P2 + (size_t)row * A_DIM)
                                      : (g_P1 + (size_t)row * A_DIM);
                    dst[a] = o;
                }
            }
        }
        __syncthreads();
    }
}

// ---------------------------------------------------------------------------
// S kernel: 8-lane cooperative per edge -> coalesced row reads (2 lines/row).
// ---------------------------------------------------------------------------
__global__ __launch_bounds__(256) void s_k(const float* __restrict__ bias,
                                           const float* __restrict__ u,
                                           const float* __restrict__ corr) {
    const int tid = threadIdx.x;
    const int lane = tid & 31;
    const int grp = lane >> 3;
    const int l = lane & 7;
    const int warp = (blockIdx.x * 256 + tid) >> 5;
    const int e = warp * 4 + grp;

    const float4 b0 = ((const float4*)bias)[l];
    const float4 b1 = ((const float4*)bias)[l + 8];
    const float4 u0 = ((const float4*)u)[l];
    const float4 u1 = ((const float4*)u)[l + 8];

    const int c = g_cp[e];
    const int fi = g_fci[e];
    const float4* p1 = (const float4*)(g_P1 + (size_t)c * A_DIM);
    const float4* p2 = (const float4*)(g_P2 + (size_t)fi * A_DIM);
    const float4 x0 = p1[l], x1 = p1[l + 8];
    const float4 y0 = p2[l], y1 = p2[l + 8];

    float t = tanh_hw(x0.x + y0.x + b0.x) * u0.x
            + tanh_hw(x0.y + y0.y + b0.y) * u0.y
            + tanh_hw(x0.z + y0.z + b0.z) * u0.z
            + tanh_hw(x0.w + y0.w + b0.w) * u0.w
            + tanh_hw(x1.x + y1.x + b1.x) * u1.x
            + tanh_hw(x1.y + y1.y + b1.y) * u1.y
            + tanh_hw(x1.z + y1.z + b1.z) * u1.z
            + tanh_hw(x1.w + y1.w + b1.w) * u1.w;

    t += __shfl_xor_sync(0xffffffffu, t, 1);
    t += __shfl_xor_sync(0xffffffffu, t, 2);
    t += __shfl_xor_sync(0xffffffffu, t, 4);
    if (l == 0) g_scores[e] = __expf(t) * corr[e];
}

// ---------------------------------------------------------------------------
// C kernel: warp per feature segment, precomputed bounds, 4-deep pipeline.
// ---------------------------------------------------------------------------
__device__ __forceinline__ const float4* emb_row(const float* feat, const float* hid, int fi) {
    return (const float4*)((fi < F_NUM) ? (feat + (size_t)fi * D_DIM)
                                        : (hid + (size_t)(fi - F_NUM) * D_DIM));
}

__global__ __launch_bounds__(256) void c_k(const float* __restrict__ feat,
                                           const float* __restrict__ hid) {
    const int lane = threadIdx.x & 31;
    const int f = blockIdx.x * 8 + (threadIdx.x >> 5);
    if (f >= F_NUM) return;

    const int lo = g_segstart[f];
    const int hiN = g_segstart[f + 1];

    float4 acc = make_float4(0.f, 0.f, 0.f, 0.f);
    float den = 0.f;
    int e = lo;
    for (; e + 4 <= hiN; e += 4) {
        const float s0 = g_scores[e + 0];
        const float s1 = g_scores[e + 1];
        const float s2 = g_scores[e + 2];
        const float s3 = g_scores[e + 3];
        const float4 v0 = emb_row(feat, hid, g_fci[e + 0])[lane];
        const float4 v1 = emb_row(feat, hid, g_fci[e + 1])[lane];
        const float4 v2 = emb_row(feat, hid, g_fci[e + 2])[lane];
        const float4 v3 = emb_row(feat, hid, g_fci[e + 3])[lane];
        acc.x += s0 * v0.x + s1 * v1.x + s2 * v2.x + s3 * v3.x;
        acc.y += s0 * v0.y + s1 * v1.y + s2 * v2.y + s3 * v3.y;
        acc.z += s0 * v0.z + s1 * v1.z + s2 * v2.z + s3 * v3.z;
        acc.w += s0 * v0.w + s1 * v1.w + s2 * v2.w + s3 * v3.w;
        den += (s0 + s1) + (s2 + s3);
    }
    for (; e < hiN; ++e) {
        const float s = g_scores[e];
        const float4 v = emb_row(feat, hid, g_fci[e])[lane];
        acc.x += s * v.x; acc.y += s * v.y; acc.z += s * v.z; acc.w += s * v.w;
        den += s;
    }
    const float inv = (den != 0.f) ? (1.f / den) : 0.f;
    float4 o = make_float4(acc.x * inv, acc.y * inv, acc.z * inv, acc.w * inv);
    ((float4*)(g_context + (size_t)f * D_DIM))[lane] = o;
}

// ---------------------------------------------------------------------------
// G kernels (EXACT R5 version): out[256,128] = values[256,F] @ context[F,128].
// 16 b-rows/block, acc[8], KSPLIT=50.
// ---------------------------------------------------------------------------
__global__ __launch_bounds__(256) void g1_k(const float* __restrict__ values) {
    const int tid = threadIdx.x;
    const int d = tid & 127;
    const int bh = tid >> 7;
    const int b0 = blockIdx.x * 16 + bh * 8;
    const int k0 = blockIdx.y * KCH;

    float acc[8];
#pragma unroll
    for (int i = 0; i < 8; ++i) acc[i] = 0.f;

    for (int k = k0; k < k0 + KCH; k += 4) {
        const float c0 = g_context[(size_t)(k + 0) * D_DIM + d];
        const float c1 = g_context[(size_t)(k + 1) * D_DIM + d];
        const float c2 = g_context[(size_t)(k + 2) * D_DIM + d];
        const float c3 = g_context[(size_t)(k + 3) * D_DIM + d];
#pragma unroll
        for (int i = 0; i < 8; ++i) {
            const float4 v = *(const float4*)(values + (size_t)(b0 + i) * F_NUM + k);
            acc[i] += v.x * c0 + v.y * c1 + v.z * c2 + v.w * c3;
        }
    }
    float* part = g_partial + (size_t)blockIdx.y * (B_NUM * D_DIM);
#pragma unroll
    for (int i = 0; i < 8; ++i) part[(size_t)(b0 + i) * D_DIM + d] = acc[i];
}

__global__ __launch_bounds__(256) void g2_k(float* __restrict__ out) {
    const int i = blockIdx.x * blockDim.x + threadIdx.x;
    if (i >= B_NUM * D_DIM) return;
    float s = 0.f;
#pragma unroll
    for (int j = 0; j < KSPLIT; ++j) s += g_partial[(size_t)j * (B_NUM * D_DIM) + i];
    out[i] = s;
}

// ---------------------------------------------------------------------------
extern "C" void kernel_launch(void* const* d_in, const int* in_sizes, int n_in,
                              void* d_out, int out_size) {
    const float* values = (const float*)d_in[0];
    const float* feat   = (const float*)d_in[1];
    const float* hid    = (const float*)d_in[2];
    const float* w      = (const float*)d_in[3];
    const float* bias   = (const float*)d_in[4];
    const float* u      = (const float*)d_in[5];
    const float* corr   = (const float*)d_in[6];
    const void*  cp     = d_in[7];
    const void*  fci    = d_in[8];
    float* out = (float*)d_out;

    detect_k<<<1, 32>>>(cp, fci);
    convseg_k<<<(E_NUM + 255) / 256, 256>>>(cp, fci);
    p_k<<<PB1 + PB2, 256>>>(feat, hid, w);
    s_k<<<S_GRID, 256>>>(bias, u, corr);
    c_k<<<F_NUM / 8, 256>>>(feat, hid);
    g1_k<<<dim3(16, KSPLIT), 256>>>(values);
    g2_k<<<(B_NUM * D_DIM + 255) / 256, 256>>>(out);
}

// round 10
// speedup vs baseline: 2.6957x; 1.3132x over previous
#include <cuda_runtime.h>

#define F_NUM 20000
#define H_NUM 40000
#define NALL  60000
#define E_NUM 640000
#define D_DIM 128
#define A_DIM 64
#define B_NUM 256
#define KSPLIT 50
#define KCH (F_NUM / KSPLIT)   // 400

// p_k tiling: 64 rows per block, processed in 8-row staged batches.
#define PT_ROWS 64
#define PB1 ((F_NUM + PT_ROWS - 1) / PT_ROWS)   // 313
#define PB2 ((NALL + PT_ROWS - 1) / PT_ROWS)    // 938

// s_k layout: 8 warps/block, 4 edges/warp -> 32 edges per block.
#define S_EDGES_PER_BLOCK 32
#define S_GRID (E_NUM / S_EDGES_PER_BLOCK)   // 20000
static_assert(S_GRID * S_EDGES_PER_BLOCK == E_NUM, "s_k grid must cover all edges");
static_assert(KSPLIT * KCH == F_NUM, "split-K must tile F exactly");
static_assert(KCH % 8 == 0, "mma k-chunk must be a multiple of 8");

// ---- scratch (static device globals; no allocation) ----
__device__ float g_P1[F_NUM * A_DIM];
__device__ float g_P2[NALL * A_DIM];
__device__ float g_scores[E_NUM];
__device__ float g_context[F_NUM * D_DIM];
__device__ int   g_cp[E_NUM];
__device__ int   g_fci[E_NUM];
__device__ int   g_is32[2];
__device__ int   g_segstart[F_NUM + 1];
__device__ float g_partial[KSPLIT * B_NUM * D_DIM];

__device__ __forceinline__ float tanh_hw(float x) {
    float y;
    asm("tanh.approx.f32 %0, %1;" : "=f"(y) : "f"(x));
    return y;
}

// tf32 helpers for 3xTF32 GEMM
__device__ __forceinline__ unsigned tf32_of(float x) {
    unsigned r;
    asm("cvt.rna.tf32.f32 %0, %1;" : "=r"(r) : "f"(x));
    return r;
}
__device__ __forceinline__ void tf32_split(float x, unsigned& hi, unsigned& lo) {
    hi = tf32_of(x);
    lo = tf32_of(x - __uint_as_float(hi));
}
__device__ __forceinline__ void mma_tf32(float* d, const unsigned* a, const unsigned* b) {
    asm volatile(
        "mma.sync.aligned.m16n8k8.row.col.f32.tf32.tf32.f32 "
        "{%0,%1,%2,%3}, {%4,%5,%6,%7}, {%8,%9}, {%0,%1,%2,%3};"
        : "+f"(d[0]), "+f"(d[1]), "+f"(d[2]), "+f"(d[3])
        : "r"(a[0]), "r"(a[1]), "r"(a[2]), "r"(a[3]), "r"(b[0]), "r"(b[1]));
}

// ---------------------------------------------------------------------------
// int32/int64 index detection (probe tail as int64; int32 data yields
// high-word >= NALL).
// ---------------------------------------------------------------------------
__global__ void detect_k(const void* cp, const void* fci) {
    if (threadIdx.x != 0 || blockIdx.x != 0) return;
    const long long* p = (const long long*)cp;
    long long m = 0;
    for (int j = 1; j <= 8; ++j) {
        long long v = p[E_NUM / 2 - j];
        if (v < 0) v = (1LL << 40);
        if (v > m) m = v;
    }
    g_is32[0] = (m >= (long long)NALL) ? 1 : 0;
    const long long* q = (const long long*)fci;
    m = 0;
    for (int j = 1; j <= 8; ++j) {
        long long v = q[E_NUM / 2 - j];
        if (v < 0) v = (1LL << 40);
        if (v > m) m = v;
    }
    g_is32[1] = (m >= (long long)NALL) ? 1 : 0;
}

// ---------------------------------------------------------------------------
// convseg_k: fused index conversion + segment-boundary fill.
// ---------------------------------------------------------------------------
__device__ __forceinline__ int idx_at(const void* p, int is32, int e) {
    return is32 ? ((const int*)p)[e] : (int)((const long long*)p)[e];
}

__global__ void convseg_k(const void* cp, const void* fci) {
    int e = blockIdx.x * blockDim.x + threadIdx.x;
    if (e >= E_NUM) return;
    const int is0 = g_is32[0], is1 = g_is32[1];
    const int c = idx_at(cp, is0, e);
    g_cp[e] = c;
    g_fci[e] = idx_at(fci, is1, e);
    const int prev = (e == 0) ? -1 : idx_at(cp, is0, e - 1);
    for (int f = prev + 1; f <= c; ++f) g_segstart[f] = e;
    if (e == E_NUM - 1)
        for (int f = c + 1; f <= F_NUM; ++f) g_segstart[f] = E_NUM;
}

// ---------------------------------------------------------------------------
// P kernel v2 (EXACT R6 version, measured 75.8us).
// ---------------------------------------------------------------------------
__global__ __launch_bounds__(256) void p_k(const float* __restrict__ feat,
                                           const float* __restrict__ hid,
                                           const float* __restrict__ w) {
    const int tid = threadIdx.x;
    const int a = tid & 63;
    const int h = tid >> 6;

    const bool reg2 = (blockIdx.x >= PB1);
    const int row0 = (reg2 ? (blockIdx.x - PB1) : blockIdx.x) * PT_ROWS;
    const int limit = reg2 ? NALL : F_NUM;
    const int wbase = reg2 ? 128 : 0;

    float wr[32];
#pragma unroll
    for (int j = 0; j < 32; ++j)
        wr[j] = w[(wbase + h * 32 + j) * A_DIM + a];

    __shared__ float4 stage[8][32];
    __shared__ float red[3][8][64];

    for (int b = 0; b < PT_ROWS / 8; ++b) {
        {
            const int rr = tid >> 5;
            const int c4 = tid & 31;
            const int row = row0 + b * 8 + rr;
            float4 v = make_float4(0.f, 0.f, 0.f, 0.f);
            if (row < limit) {
                const float* src;
                if (!reg2) src = feat + (size_t)row * D_DIM;
                else       src = (row < F_NUM) ? (feat + (size_t)row * D_DIM)
                                               : (hid + (size_t)(row - F_NUM) * D_DIM);
                v = ((const float4*)src)[c4];
            }
            stage[rr][c4] = v;
        }
        __syncthreads();

        float part[8];
#pragma unroll
        for (int rr = 0; rr < 8; ++rr) {
            const float4* s4 = &stage[rr][h * 8];
            float a0 = 0.f, a1 = 0.f, a2 = 0.f, a3 = 0.f;
#pragma unroll
            for (int j = 0; j < 8; ++j) {
                const float4 v = s4[j];
                a0 += v.x * wr[4 * j + 0];
                a1 += v.y * wr[4 * j + 1];
                a2 += v.z * wr[4 * j + 2];
                a3 += v.w * wr[4 * j + 3];
            }
            part[rr] = (a0 + a1) + (a2 + a3);
        }
        if (h) {
#pragma unroll
            for (int rr = 0; rr < 8; ++rr) red[h - 1][rr][a] = part[rr];
        }
        __syncthreads();
        if (!h) {
#pragma unroll
            for (int rr = 0; rr < 8; ++rr) {
                const int row = row0 + b * 8 + rr;
                if (row < limit) {
                    const float o = (part[rr] + red[0][rr][a])
                                  + (red[1][rr][a] + red[2][rr][a]);
                    float* dst = reg2 ? (g_P2 + (size_t)row * A_DIM)
                                      : (g_P1 + (size_t)row * A_DIM);
                    dst[a] = o;
                }
            }
        }
        __syncthreads();
    }
}

// ---------------------------------------------------------------------------
// S kernel: 8-lane cooperative per edge (EXACT R8 version, measured 36.4us).
// ---------------------------------------------------------------------------
__global__ __launch_bounds__(256) void s_k(const float* __restrict__ bias,
                                           const float* __restrict__ u,
                                           const float* __restrict__ corr) {
    const int tid = threadIdx.x;
    const int lane = tid & 31;
    const int grp = lane >> 3;
    const int l = lane & 7;
    const int warp = (blockIdx.x * 256 + tid) >> 5;
    const int e = warp * 4 + grp;

    const float4 b0 = ((const float4*)bias)[l];
    const float4 b1 = ((const float4*)bias)[l + 8];
    const float4 u0 = ((const float4*)u)[l];
    const float4 u1 = ((const float4*)u)[l + 8];

    const int c = g_cp[e];
    const int fi = g_fci[e];
    const float4* p1 = (const float4*)(g_P1 + (size_t)c * A_DIM);
    const float4* p2 = (const float4*)(g_P2 + (size_t)fi * A_DIM);
    const float4 x0 = p1[l], x1 = p1[l + 8];
    const float4 y0 = p2[l], y1 = p2[l + 8];

    float t = tanh_hw(x0.x + y0.x + b0.x) * u0.x
            + tanh_hw(x0.y + y0.y + b0.y) * u0.y
            + tanh_hw(x0.z + y0.z + b0.z) * u0.z
            + tanh_hw(x0.w + y0.w + b0.w) * u0.w
            + tanh_hw(x1.x + y1.x + b1.x) * u1.x
            + tanh_hw(x1.y + y1.y + b1.y) * u1.y
            + tanh_hw(x1.z + y1.z + b1.z) * u1.z
            + tanh_hw(x1.w + y1.w + b1.w) * u1.w;

    t += __shfl_xor_sync(0xffffffffu, t, 1);
    t += __shfl_xor_sync(0xffffffffu, t, 2);
    t += __shfl_xor_sync(0xffffffffu, t, 4);
    if (l == 0) g_scores[e] = __expf(t) * corr[e];
}

// ---------------------------------------------------------------------------
// C kernel: warp per feature segment (EXACT R8 version).
// ---------------------------------------------------------------------------
__device__ __forceinline__ const float4* emb_row(const float* feat, const float* hid, int fi) {
    return (const float4*)((fi < F_NUM) ? (feat + (size_t)fi * D_DIM)
                                        : (hid + (size_t)(fi - F_NUM) * D_DIM));
}

__global__ __launch_bounds__(256) void c_k(const float* __restrict__ feat,
                                           const float* __restrict__ hid) {
    const int lane = threadIdx.x & 31;
    const int f = blockIdx.x * 8 + (threadIdx.x >> 5);
    if (f >= F_NUM) return;

    const int lo = g_segstart[f];
    const int hiN = g_segstart[f + 1];

    float4 acc = make_float4(0.f, 0.f, 0.f, 0.f);
    float den = 0.f;
    int e = lo;
    for (; e + 4 <= hiN; e += 4) {
        const float s0 = g_scores[e + 0];
        const float s1 = g_scores[e + 1];
        const float s2 = g_scores[e + 2];
        const float s3 = g_scores[e + 3];
        const float4 v0 = emb_row(feat, hid, g_fci[e + 0])[lane];
        const float4 v1 = emb_row(feat, hid, g_fci[e + 1])[lane];
        const float4 v2 = emb_row(feat, hid, g_fci[e + 2])[lane];
        const float4 v3 = emb_row(feat, hid, g_fci[e + 3])[lane];
        acc.x += s0 * v0.x + s1 * v1.x + s2 * v2.x + s3 * v3.x;
        acc.y += s0 * v0.y + s1 * v1.y + s2 * v2.y + s3 * v3.y;
        acc.z += s0 * v0.z + s1 * v1.z + s2 * v2.z + s3 * v3.z;
        acc.w += s0 * v0.w + s1 * v1.w + s2 * v2.w + s3 * v3.w;
        den += (s0 + s1) + (s2 + s3);
    }
    for (; e < hiN; ++e) {
        const float s = g_scores[e];
        const float4 v = emb_row(feat, hid, g_fci[e])[lane];
        acc.x += s * v.x; acc.y += s * v.y; acc.z += s * v.z; acc.w += s * v.w;
        den += s;
    }
    const float inv = (den != 0.f) ? (1.f / den) : 0.f;
    float4 o = make_float4(acc.x * inv, acc.y * inv, acc.z * inv, acc.w * inv);
    ((float4*)(g_context + (size_t)f * D_DIM))[lane] = o;
}

// ---------------------------------------------------------------------------
// g1 via tensor cores: out[256,128] = values[256,F] @ g_context[F,128],
// 3xTF32 mma.sync.m16n8k8 (hi*hi + hi*lo + lo*hi), fp32 accumulate.
// g_context referenced DIRECTLY inside the kernel (device symbol as a host
// kernel argument is UB -- the R9 bug).
// Block: 8 warps = 4 M-groups x 2 N-groups; block tile 128M x 64N;
// warp tile 32M x 32N (2 m-tiles x 4 n-tiles). Grid: (4, KSPLIT).
// Deterministic: fixed k-order per split, partials reduced by g2_k.
// ---------------------------------------------------------------------------
__global__ __launch_bounds__(256) void g1mma_k(const float* __restrict__ V) {
    const float* __restrict__ C = g_context;
    const int lane = threadIdx.x & 31;
    const int w = threadIdx.x >> 5;
    const int mg = w & 3;          // M group 0..3
    const int ng = w >> 2;         // N group 0..1
    const int mblk = blockIdx.x & 1;
    const int nblk = blockIdx.x >> 1;
    const int m_warp = mblk * 128 + mg * 32;
    const int n_warp = nblk * 64 + ng * 32;
    const int k0 = blockIdx.y * KCH;

    const int gid = lane >> 2;     // 0..7
    const int tig = lane & 3;      // 0..3

    float acc[2][4][4];
#pragma unroll
    for (int mt = 0; mt < 2; ++mt)
#pragma unroll
        for (int t = 0; t < 4; ++t)
#pragma unroll
            for (int r = 0; r < 4; ++r) acc[mt][t][r] = 0.f;

    for (int k = k0; k < k0 + KCH; k += 8) {
        // A fragments (values, row-major 16x8 per m-tile), hi/lo split
        unsigned ah[2][4], al[2][4];
#pragma unroll
        for (int mt = 0; mt < 2; ++mt) {
            const int m = m_warp + mt * 16;
            const float a0 = __ldg(V + (size_t)(m + gid)     * F_NUM + k + tig);
            const float a1 = __ldg(V + (size_t)(m + gid + 8) * F_NUM + k + tig);
            const float a2 = __ldg(V + (size_t)(m + gid)     * F_NUM + k + tig + 4);
            const float a3 = __ldg(V + (size_t)(m + gid + 8) * F_NUM + k + tig + 4);
            tf32_split(a0, ah[mt][0], al[mt][0]);
            tf32_split(a1, ah[mt][1], al[mt][1]);
            tf32_split(a2, ah[mt][2], al[mt][2]);
            tf32_split(a3, ah[mt][3], al[mt][3]);
        }
        // B fragments (context, K x N: 8x8 per n-tile), hi/lo split
        unsigned bh[4][2], bl[4][2];
#pragma unroll
        for (int t = 0; t < 4; ++t) {
            const int n = n_warp + t * 8;
            const float b0 = C[(size_t)(k + tig)     * D_DIM + n + gid];
            const float b1 = C[(size_t)(k + 4 + tig) * D_DIM + n + gid];
            tf32_split(b0, bh[t][0], bl[t][0]);
            tf32_split(b1, bh[t][1], bl[t][1]);
        }
        // 3xTF32 mma
#pragma unroll
        for (int mt = 0; mt < 2; ++mt) {
#pragma unroll
            for (int t = 0; t < 4; ++t) {
                mma_tf32(acc[mt][t], ah[mt], bh[t]);
                mma_tf32(acc[mt][t], ah[mt], bl[t]);
                mma_tf32(acc[mt][t], al[mt], bh[t]);
            }
        }
    }

    // epilogue: write warp tile into this k-split's partial slice
    float* part = g_partial + (size_t)blockIdx.y * (B_NUM * D_DIM);
#pragma unroll
    for (int mt = 0; mt < 2; ++mt) {
#pragma unroll
        for (int t = 0; t < 4; ++t) {
            const int row0 = m_warp + mt * 16 + gid;
            const int col  = n_warp + t * 8 + tig * 2;
            part[(size_t)row0 * D_DIM + col]           = acc[mt][t][0];
            part[(size_t)row0 * D_DIM + col + 1]       = acc[mt][t][1];
            part[(size_t)(row0 + 8) * D_DIM + col]     = acc[mt][t][2];
            part[(size_t)(row0 + 8) * D_DIM + col + 1] = acc[mt][t][3];
        }
    }
}

__global__ __launch_bounds__(256) void g2_k(float* __restrict__ out) {
    const int i = blockIdx.x * blockDim.x + threadIdx.x;
    if (i >= B_NUM * D_DIM) return;
    float s = 0.f;
#pragma unroll
    for (int j = 0; j < KSPLIT; ++j) s += g_partial[(size_t)j * (B_NUM * D_DIM) + i];
    out[i] = s;
}

// ---------------------------------------------------------------------------
extern "C" void kernel_launch(void* const* d_in, const int* in_sizes, int n_in,
                              void* d_out, int out_size) {
    const float* values = (const float*)d_in[0];
    const float* feat   = (const float*)d_in[1];
    const float* hid    = (const float*)d_in[2];
    const float* w      = (const float*)d_in[3];
    const float* bias   = (const float*)d_in[4];
    const float* u      = (const float*)d_in[5];
    const float* corr   = (const float*)d_in[6];
    const void*  cp     = d_in[7];
    const void*  fci    = d_in[8];
    float* out = (float*)d_out;

    detect_k<<<1, 32>>>(cp, fci);
    convseg_k<<<(E_NUM + 255) / 256, 256>>>(cp, fci);
    p_k<<<PB1 + PB2, 256>>>(feat, hid, w);
    s_k<<<S_GRID, 256>>>(bias, u, corr);
    c_k<<<F_NUM / 8, 256>>>(feat, hid);
    g1mma_k<<<dim3(4, KSPLIT), 256>>>(values);
    g2_k<<<(B_NUM * D_DIM + 255) / 256, 256>>>(out);
}

// round 11
// speedup vs baseline: 2.9280x; 1.0862x over previous
#include <cuda_runtime.h>

#define F_NUM 20000
#define H_NUM 40000
#define NALL  60000
#define E_NUM 640000
#define D_DIM 128
#define A_DIM 64
#define B_NUM 256
#define KSPLIT 50
#define KCH (F_NUM / KSPLIT)   // 400

// pmma tiling: 128 rows per block (8 warps x 16 rows).
#define PM_ROWS 128
#define PB1M ((F_NUM + PM_ROWS - 1) / PM_ROWS)   // 157
#define PB2M ((NALL + PM_ROWS - 1) / PM_ROWS)    // 469

// s_k layout: 8 warps/block, 4 edges/warp -> 32 edges per block.
#define S_EDGES_PER_BLOCK 32
#define S_GRID (E_NUM / S_EDGES_PER_BLOCK)   // 20000
static_assert(S_GRID * S_EDGES_PER_BLOCK == E_NUM, "s_k grid must cover all edges");
static_assert(KSPLIT * KCH == F_NUM, "split-K must tile F exactly");
static_assert(KCH % 8 == 0, "mma k-chunk must be a multiple of 8");

// ---- scratch (static device globals; no allocation) ----
__device__ float g_P1[F_NUM * A_DIM];
__device__ float g_P2[NALL * A_DIM];
__device__ float g_scores[E_NUM];
__device__ float g_context[F_NUM * D_DIM];
__device__ int   g_cp[E_NUM];
__device__ int   g_fci[E_NUM];
__device__ int   g_is32[2];
__device__ int   g_segstart[F_NUM + 1];
__device__ float g_partial[KSPLIT * B_NUM * D_DIM];

__device__ __forceinline__ float tanh_hw(float x) {
    float y;
    asm("tanh.approx.f32 %0, %1;" : "=f"(y) : "f"(x));
    return y;
}

// tf32 helpers for 3xTF32 GEMM
__device__ __forceinline__ unsigned tf32_of(float x) {
    unsigned r;
    asm("cvt.rna.tf32.f32 %0, %1;" : "=r"(r) : "f"(x));
    return r;
}
__device__ __forceinline__ void tf32_split(float x, unsigned& hi, unsigned& lo) {
    hi = tf32_of(x);
    lo = tf32_of(x - __uint_as_float(hi));
}
__device__ __forceinline__ void mma_tf32(float* d, const unsigned* a, const unsigned* b) {
    asm volatile(
        "mma.sync.aligned.m16n8k8.row.col.f32.tf32.tf32.f32 "
        "{%0,%1,%2,%3}, {%4,%5,%6,%7}, {%8,%9}, {%0,%1,%2,%3};"
        : "+f"(d[0]), "+f"(d[1]), "+f"(d[2]), "+f"(d[3])
        : "r"(a[0]), "r"(a[1]), "r"(a[2]), "r"(a[3]), "r"(b[0]), "r"(b[1]));
}

// ---------------------------------------------------------------------------
// int32/int64 index detection.
// ---------------------------------------------------------------------------
__global__ void detect_k(const void* cp, const void* fci) {
    if (threadIdx.x != 0 || blockIdx.x != 0) return;
    const long long* p = (const long long*)cp;
    long long m = 0;
    for (int j = 1; j <= 8; ++j) {
        long long v = p[E_NUM / 2 - j];
        if (v < 0) v = (1LL << 40);
        if (v > m) m = v;
    }
    g_is32[0] = (m >= (long long)NALL) ? 1 : 0;
    const long long* q = (const long long*)fci;
    m = 0;
    for (int j = 1; j <= 8; ++j) {
        long long v = q[E_NUM / 2 - j];
        if (v < 0) v = (1LL << 40);
        if (v > m) m = v;
    }
    g_is32[1] = (m >= (long long)NALL) ? 1 : 0;
}

// ---------------------------------------------------------------------------
// convseg_k: fused index conversion + segment-boundary fill.
// ---------------------------------------------------------------------------
__device__ __forceinline__ int idx_at(const void* p, int is32, int e) {
    return is32 ? ((const int*)p)[e] : (int)((const long long*)p)[e];
}

__global__ void convseg_k(const void* cp, const void* fci) {
    int e = blockIdx.x * blockDim.x + threadIdx.x;
    if (e >= E_NUM) return;
    const int is0 = g_is32[0], is1 = g_is32[1];
    const int c = idx_at(cp, is0, e);
    g_cp[e] = c;
    g_fci[e] = idx_at(fci, is1, e);
    const int prev = (e == 0) ? -1 : idx_at(cp, is0, e - 1);
    for (int f = prev + 1; f <= c; ++f) g_segstart[f] = e;
    if (e == E_NUM - 1)
        for (int f = c + 1; f <= F_NUM; ++f) g_segstart[f] = E_NUM;
}

// ---------------------------------------------------------------------------
// pmma_k: P1/P2 via tensor cores (same 3xTF32 recipe as g1mma_k).
// P1[20000,64] = feat[20000,128] @ W[0:128,:]
// P2[60000,64] = all[60000,128]  @ W[128:256,:]
// Block: 8 warps x 16 rows = 128 rows; warp tile 16M x 64N (8 n-tiles).
// ---------------------------------------------------------------------------
__device__ __forceinline__ float emb_at(const float* feat, const float* hid,
                                        bool reg2, int limit, int row, int col) {
    if (row >= limit) return 0.f;
    const float* src;
    if (!reg2) src = feat + (size_t)row * D_DIM;
    else       src = (row < F_NUM) ? (feat + (size_t)row * D_DIM)
                                   : (hid + (size_t)(row - F_NUM) * D_DIM);
    return __ldg(src + col);
}

__global__ __launch_bounds__(256) void pmma_k(const float* __restrict__ feat,
                                              const float* __restrict__ hid,
                                              const float* __restrict__ w) {
    const int lane = threadIdx.x & 31;
    const int wid = threadIdx.x >> 5;

    const bool reg2 = (blockIdx.x >= PB1M);
    const int row0 = (reg2 ? (blockIdx.x - PB1M) : blockIdx.x) * PM_ROWS + wid * 16;
    const int limit = reg2 ? NALL : F_NUM;
    const int wbase = reg2 ? 128 : 0;
    float* const P = reg2 ? g_P2 : g_P1;

    const int gid = lane >> 2;     // 0..7
    const int tig = lane & 3;      // 0..3

    float acc[8][4];
#pragma unroll
    for (int t = 0; t < 8; ++t)
#pragma unroll
        for (int r = 0; r < 4; ++r) acc[t][r] = 0.f;

    for (int k = 0; k < D_DIM; k += 8) {
        // A fragments (emb rows, row-major 16x8), hi/lo split
        unsigned ah[4], al[4];
        {
            const float a0 = emb_at(feat, hid, reg2, limit, row0 + gid,     k + tig);
            const float a1 = emb_at(feat, hid, reg2, limit, row0 + gid + 8, k + tig);
            const float a2 = emb_at(feat, hid, reg2, limit, row0 + gid,     k + tig + 4);
            const float a3 = emb_at(feat, hid, reg2, limit, row0 + gid + 8, k + tig + 4);
            tf32_split(a0, ah[0], al[0]);
            tf32_split(a1, ah[1], al[1]);
            tf32_split(a2, ah[2], al[2]);
            tf32_split(a3, ah[3], al[3]);
        }
        // B fragments (W, K x N: 8x8 per n-tile), hi/lo split
        unsigned bh[8][2], bl[8][2];
#pragma unroll
        for (int t = 0; t < 8; ++t) {
            const int n = t * 8;
            const float b0 = __ldg(w + (size_t)(wbase + k + tig)     * A_DIM + n + gid);
            const float b1 = __ldg(w + (size_t)(wbase + k + 4 + tig) * A_DIM + n + gid);
            tf32_split(b0, bh[t][0], bl[t][0]);
            tf32_split(b1, bh[t][1], bl[t][1]);
        }
        // 3xTF32 mma
#pragma unroll
        for (int t = 0; t < 8; ++t) {
            mma_tf32(acc[t], ah, bh[t]);
            mma_tf32(acc[t], ah, bl[t]);
            mma_tf32(acc[t], al, bh[t]);
        }
    }

    // epilogue: float2 stores, rows guarded
    const int r0 = row0 + gid;
    const int r1 = row0 + gid + 8;
#pragma unroll
    for (int t = 0; t < 8; ++t) {
        const int col = t * 8 + tig * 2;
        if (r0 < limit)
            *(float2*)(P + (size_t)r0 * A_DIM + col) = make_float2(acc[t][0], acc[t][1]);
        if (r1 < limit)
            *(float2*)(P + (size_t)r1 * A_DIM + col) = make_float2(acc[t][2], acc[t][3]);
    }
}

// ---------------------------------------------------------------------------
// S kernel: 8-lane cooperative per edge (EXACT R8 version, measured 36.4us).
// ---------------------------------------------------------------------------
__global__ __launch_bounds__(256) void s_k(const float* __restrict__ bias,
                                           const float* __restrict__ u,
                                           const float* __restrict__ corr) {
    const int tid = threadIdx.x;
    const int lane = tid & 31;
    const int grp = lane >> 3;
    const int l = lane & 7;
    const int warp = (blockIdx.x * 256 + tid) >> 5;
    const int e = warp * 4 + grp;

    const float4 b0 = ((const float4*)bias)[l];
    const float4 b1 = ((const float4*)bias)[l + 8];
    const float4 u0 = ((const float4*)u)[l];
    const float4 u1 = ((const float4*)u)[l + 8];

    const int c = g_cp[e];
    const int fi = g_fci[e];
    const float4* p1 = (const float4*)(g_P1 + (size_t)c * A_DIM);
    const float4* p2 = (const float4*)(g_P2 + (size_t)fi * A_DIM);
    const float4 x0 = p1[l], x1 = p1[l + 8];
    const float4 y0 = p2[l], y1 = p2[l + 8];

    float t = tanh_hw(x0.x + y0.x + b0.x) * u0.x
            + tanh_hw(x0.y + y0.y + b0.y) * u0.y
            + tanh_hw(x0.z + y0.z + b0.z) * u0.z
            + tanh_hw(x0.w + y0.w + b0.w) * u0.w
            + tanh_hw(x1.x + y1.x + b1.x) * u1.x
            + tanh_hw(x1.y + y1.y + b1.y) * u1.y
            + tanh_hw(x1.z + y1.z + b1.z) * u1.z
            + tanh_hw(x1.w + y1.w + b1.w) * u1.w;

    t += __shfl_xor_sync(0xffffffffu, t, 1);
    t += __shfl_xor_sync(0xffffffffu, t, 2);
    t += __shfl_xor_sync(0xffffffffu, t, 4);
    if (l == 0) g_scores[e] = __expf(t) * corr[e];
}

// ---------------------------------------------------------------------------
// C kernel: warp per feature segment (EXACT R8 version).
// ---------------------------------------------------------------------------
__device__ __forceinline__ const float4* emb_row(const float* feat, const float* hid, int fi) {
    return (const float4*)((fi < F_NUM) ? (feat + (size_t)fi * D_DIM)
                                        : (hid + (size_t)(fi - F_NUM) * D_DIM));
}

__global__ __launch_bounds__(256) void c_k(const float* __restrict__ feat,
                                           const float* __restrict__ hid) {
    const int lane = threadIdx.x & 31;
    const int f = blockIdx.x * 8 + (threadIdx.x >> 5);
    if (f >= F_NUM) return;

    const int lo = g_segstart[f];
    const int hiN = g_segstart[f + 1];

    float4 acc = make_float4(0.f, 0.f, 0.f, 0.f);
    float den = 0.f;
    int e = lo;
    for (; e + 4 <= hiN; e += 4) {
        const float s0 = g_scores[e + 0];
        const float s1 = g_scores[e + 1];
        const float s2 = g_scores[e + 2];
        const float s3 = g_scores[e + 3];
        const float4 v0 = emb_row(feat, hid, g_fci[e + 0])[lane];
        const float4 v1 = emb_row(feat, hid, g_fci[e + 1])[lane];
        const float4 v2 = emb_row(feat, hid, g_fci[e + 2])[lane];
        const float4 v3 = emb_row(feat, hid, g_fci[e + 3])[lane];
        acc.x += s0 * v0.x + s1 * v1.x + s2 * v2.x + s3 * v3.x;
        acc.y += s0 * v0.y + s1 * v1.y + s2 * v2.y + s3 * v3.y;
        acc.z += s0 * v0.z + s1 * v1.z + s2 * v2.z + s3 * v3.z;
        acc.w += s0 * v0.w + s1 * v1.w + s2 * v2.w + s3 * v3.w;
        den += (s0 + s1) + (s2 + s3);
    }
    for (; e < hiN; ++e) {
        const float s = g_scores[e];
        const float4 v = emb_row(feat, hid, g_fci[e])[lane];
        acc.x += s * v.x; acc.y += s * v.y; acc.z += s * v.z; acc.w += s * v.w;
        den += s;
    }
    const float inv = (den != 0.f) ? (1.f / den) : 0.f;
    float4 o = make_float4(acc.x * inv, acc.y * inv, acc.z * inv, acc.w * inv);
    ((float4*)(g_context + (size_t)f * D_DIM))[lane] = o;
}

// ---------------------------------------------------------------------------
// g1 via tensor cores (EXACT R10 version): 3xTF32 mma, partials + g2 reduce.
// ---------------------------------------------------------------------------
__global__ __launch_bounds__(256) void g1mma_k(const float* __restrict__ V) {
    const float* __restrict__ C = g_context;
    const int lane = threadIdx.x & 31;
    const int w = threadIdx.x >> 5;
    const int mg = w & 3;
    const int ng = w >> 2;
    const int mblk = blockIdx.x & 1;
    const int nblk = blockIdx.x >> 1;
    const int m_warp = mblk * 128 + mg * 32;
    const int n_warp = nblk * 64 + ng * 32;
    const int k0 = blockIdx.y * KCH;

    const int gid = lane >> 2;
    const int tig = lane & 3;

    float acc[2][4][4];
#pragma unroll
    for (int mt = 0; mt < 2; ++mt)
#pragma unroll
        for (int t = 0; t < 4; ++t)
#pragma unroll
            for (int r = 0; r < 4; ++r) acc[mt][t][r] = 0.f;

    for (int k = k0; k < k0 + KCH; k += 8) {
        unsigned ah[2][4], al[2][4];
#pragma unroll
        for (int mt = 0; mt < 2; ++mt) {
            const int m = m_warp + mt * 16;
            const float a0 = __ldg(V + (size_t)(m + gid)     * F_NUM + k + tig);
            const float a1 = __ldg(V + (size_t)(m + gid + 8) * F_NUM + k + tig);
            const float a2 = __ldg(V + (size_t)(m + gid)     * F_NUM + k + tig + 4);
            const float a3 = __ldg(V + (size_t)(m + gid + 8) * F_NUM + k + tig + 4);
            tf32_split(a0, ah[mt][0], al[mt][0]);
            tf32_split(a1, ah[mt][1], al[mt][1]);
            tf32_split(a2, ah[mt][2], al[mt][2]);
            tf32_split(a3, ah[mt][3], al[mt][3]);
        }
        unsigned bh[4][2], bl[4][2];
#pragma unroll
        for (int t = 0; t < 4; ++t) {
            const int n = n_warp + t * 8;
            const float b0 = C[(size_t)(k + tig)     * D_DIM + n + gid];
            const float b1 = C[(size_t)(k + 4 + tig) * D_DIM + n + gid];
            tf32_split(b0, bh[t][0], bl[t][0]);
            tf32_split(b1, bh[t][1], bl[t][1]);
        }
#pragma unroll
        for (int mt = 0; mt < 2; ++mt) {
#pragma unroll
            for (int t = 0; t < 4; ++t) {
                mma_tf32(acc[mt][t], ah[mt], bh[t]);
                mma_tf32(acc[mt][t], ah[mt], bl[t]);
                mma_tf32(acc[mt][t], al[mt], bh[t]);
            }
        }
    }

    float* part = g_partial + (size_t)blockIdx.y * (B_NUM * D_DIM);
#pragma unroll
    for (int mt = 0; mt < 2; ++mt) {
#pragma unroll
        for (int t = 0; t < 4; ++t) {
            const int row0 = m_warp + mt * 16 + gid;
            const int col  = n_warp + t * 8 + tig * 2;
            part[(size_t)row0 * D_DIM + col]           = acc[mt][t][0];
            part[(size_t)row0 * D_DIM + col + 1]       = acc[mt][t][1];
            part[(size_t)(row0 + 8) * D_DIM + col]     = acc[mt][t][2];
            part[(size_t)(row0 + 8) * D_DIM + col + 1] = acc[mt][t][3];
        }
    }
}

__global__ __launch_bounds__(256) void g2_k(float* __restrict__ out) {
    const int i = blockIdx.x * blockDim.x + threadIdx.x;
    if (i >= B_NUM * D_DIM) return;
    float s = 0.f;
#pragma unroll
    for (int j = 0; j < KSPLIT; ++j) s += g_partial[(size_t)j * (B_NUM * D_DIM) + i];
    out[i] = s;
}

// ---------------------------------------------------------------------------
extern "C" void kernel_launch(void* const* d_in, const int* in_sizes, int n_in,
                              void* d_out, int out_size) {
    const float* values = (const float*)d_in[0];
    const float* feat   = (const float*)d_in[1];
    const float* hid    = (const float*)d_in[2];
    const float* w      = (const float*)d_in[3];
    const float* bias   = (const float*)d_in[4];
    const float* u      = (const float*)d_in[5];
    const float* corr   = (const float*)d_in[6];
    const void*  cp     = d_in[7];
    const void*  fci    = d_in[8];
    float* out = (float*)d_out;

    detect_k<<<1, 32>>>(cp, fci);
    convseg_k<<<(E_NUM + 255) / 256, 256>>>(cp, fci);
    pmma_k<<<PB1M + PB2M, 256>>>(feat, hid, w);
    s_k<<<S_GRID, 256>>>(bias, u, corr);
    c_k<<<F_NUM / 8, 256>>>(feat, hid);
    g1mma_k<<<dim3(4, KSPLIT), 256>>>(values);
    g2_k<<<(B_NUM * D_DIM + 255) / 256, 256>>>(out);
}